// round 3
// baseline (speedup 1.0000x reference)
#include <cuda_runtime.h>

// ---------------------------------------------------------------------------
// Sparse-conv backbone:
//   x4 = [geo | col]                                  (n0, 4)
//   X1 = relu(conv_k125(x4, w0, m1))                  (n1, 32)
//   2x BasicBlock(X1, w_e1, m2)                       (n1, 32)
//   X2 = conv_k27(X1, w2, m3)                         (n2, 64)
//   2x BasicBlock(X2, w_e2, m4)                       (n2, 64)  -> d_out
//
// Key fact: out_map[k][j] is j (or dropped sentinel), so every conv is a
// pure gather-GEMM per output row; validity check is in_map[k][j] < n_in.
// ---------------------------------------------------------------------------

#define MAXN 80000
#define BN_EPS 1e-5f

__device__ float g_X1[MAXN * 32];
__device__ float g_T1[MAXN * 32];
__device__ float g_U1[MAXN * 32];
__device__ float g_X2[MAXN * 64];
__device__ float g_T2[MAXN * 64];
__device__ float g_U2[MAXN * 64];
__device__ float g_stats[8 * 128];   // 8 BN-conv regions: [sum(C) | sumsq(C)]

// ---------------------------------------------------------------------------
__global__ void zero_stats_kernel() {
    g_stats[threadIdx.x] = 0.0f;     // launched with 1024 threads
}

// ---------------------------------------------------------------------------
// conv0: K=125, Cin=4 (gathered from geo/col), Cout=32, fused ReLU.
// Full w0 (125*4*32 floats = 64000 B) staged in dynamic shared memory.
__global__ void conv0_kernel(const float* __restrict__ geo,
                             const float* __restrict__ col,
                             const float* __restrict__ W,
                             const int*  __restrict__ imap,
                             int n_out, int n_in,
                             float* __restrict__ y) {
    extern __shared__ float wsh[];   // 16000 floats
    for (int i = threadIdx.x; i < 125 * 4 * 32; i += blockDim.x) wsh[i] = W[i];
    __syncthreads();

    int r = blockIdx.x * blockDim.x + threadIdx.x;
    if (r >= n_out) return;

    float acc[32];
#pragma unroll
    for (int c = 0; c < 32; c++) acc[c] = 0.0f;

    for (int k = 0; k < 125; k++) {
        int im = imap[(size_t)k * n_out + r];
        if (im >= n_in) continue;
        float xr[4];
        xr[0] = geo[im];
        xr[1] = col[3 * im + 0];
        xr[2] = col[3 * im + 1];
        xr[3] = col[3 * im + 2];
        const float4* w4 = reinterpret_cast<const float4*>(wsh + k * 128);
#pragma unroll
        for (int ci = 0; ci < 4; ci++) {
            float xv = xr[ci];
#pragma unroll
            for (int j = 0; j < 8; j++) {
                float4 w = w4[ci * 8 + j];
                acc[4 * j + 0] = fmaf(xv, w.x, acc[4 * j + 0]);
                acc[4 * j + 1] = fmaf(xv, w.y, acc[4 * j + 1]);
                acc[4 * j + 2] = fmaf(xv, w.z, acc[4 * j + 2]);
                acc[4 * j + 3] = fmaf(xv, w.w, acc[4 * j + 3]);
            }
        }
    }

    float4* yp = reinterpret_cast<float4*>(y + (size_t)r * 32);
#pragma unroll
    for (int j = 0; j < 8; j++) {
        yp[j] = make_float4(fmaxf(acc[4 * j + 0], 0.0f),
                            fmaxf(acc[4 * j + 1], 0.0f),
                            fmaxf(acc[4 * j + 2], 0.0f),
                            fmaxf(acc[4 * j + 3], 0.0f));
    }
}

// ---------------------------------------------------------------------------
// Generic K=27 gather-GEMM. blockDim = 128. TPR threads cooperate on one
// output row (each owns CPT = COUT/TPR contiguous output channels).
// W[k] staged per-k in static shared; x row prefetched to registers.
// Optional fused BN statistics (sum, sumsq per channel) via shuffle+atomics.
template <int CIN, int COUT, int TPR>
__global__ void conv_kernel(const float* __restrict__ x,
                            const float* __restrict__ W,
                            const int*  __restrict__ imap,
                            int n_out, int n_in,
                            float* __restrict__ y,
                            float* __restrict__ statp) {
    constexpr int CPT = COUT / TPR;
    constexpr int K = 27;
    __shared__ float wsh[CIN * COUT];

    const int tid  = threadIdx.x;
    const int part = tid % TPR;                       // which cout group
    const int r    = blockIdx.x * (128 / TPR) + tid / TPR;
    const bool active = (r < n_out);

    float acc[CPT];
#pragma unroll
    for (int c = 0; c < CPT; c++) acc[c] = 0.0f;

    for (int k = 0; k < K; k++) {
        __syncthreads();
        {   // cooperative float4 stage of W[k]
            const float4* Wg = reinterpret_cast<const float4*>(W + (size_t)k * CIN * COUT);
            float4* ws4 = reinterpret_cast<float4*>(wsh);
            for (int i = tid; i < (CIN * COUT) / 4; i += 128) ws4[i] = Wg[i];
        }
        __syncthreads();
        if (!active) continue;
        int im = imap[(size_t)k * n_out + r];
        if (im >= n_in) continue;

        float xr[CIN];
        const float4* xp = reinterpret_cast<const float4*>(x + (size_t)im * CIN);
#pragma unroll
        for (int i = 0; i < CIN / 4; i++) {
            float4 v = xp[i];
            xr[4 * i + 0] = v.x; xr[4 * i + 1] = v.y;
            xr[4 * i + 2] = v.z; xr[4 * i + 3] = v.w;
        }
#pragma unroll
        for (int ci = 0; ci < CIN; ci++) {
            const float4* wrow =
                reinterpret_cast<const float4*>(wsh + ci * COUT + part * CPT);
            float xv = xr[ci];
#pragma unroll
            for (int j = 0; j < CPT / 4; j++) {
                float4 w = wrow[j];
                acc[4 * j + 0] = fmaf(xv, w.x, acc[4 * j + 0]);
                acc[4 * j + 1] = fmaf(xv, w.y, acc[4 * j + 1]);
                acc[4 * j + 2] = fmaf(xv, w.z, acc[4 * j + 2]);
                acc[4 * j + 3] = fmaf(xv, w.w, acc[4 * j + 3]);
            }
        }
    }

    if (active) {
        float4* yp = reinterpret_cast<float4*>(y + (size_t)r * COUT + part * CPT);
#pragma unroll
        for (int j = 0; j < CPT / 4; j++)
            yp[j] = make_float4(acc[4 * j + 0], acc[4 * j + 1],
                                acc[4 * j + 2], acc[4 * j + 3]);
    }

    if (statp != nullptr) {
        // per-channel sum / sumsq, reduced within warp (stride TPR), then atomics
#pragma unroll
        for (int c = 0; c < CPT; c++) {
            float v  = active ? acc[c] : 0.0f;
            float s  = v;
            float s2 = v * v;
#pragma unroll
            for (int off = TPR; off < 32; off <<= 1) {
                s  += __shfl_down_sync(0xffffffffu, s,  off);
                s2 += __shfl_down_sync(0xffffffffu, s2, off);
            }
            if ((tid & 31) < TPR) {
                atomicAdd(&statp[part * CPT + c],        s);
                atomicAdd(&statp[COUT + part * CPT + c], s2);
            }
        }
    }
}

// ---------------------------------------------------------------------------
// Elementwise BN apply (+ optional residual, + optional ReLU).
// stats: [sum(C) | sumsq(C)] accumulated over n rows.
__global__ void bn_apply_kernel(const float* __restrict__ y,
                                const float* __restrict__ stats,
                                const float* __restrict__ g,
                                const float* __restrict__ b,
                                const float* __restrict__ res,
                                float* __restrict__ out,
                                int n, int C, int relu) {
    int idx = blockIdx.x * blockDim.x + threadIdx.x;
    if (idx >= n * C) return;
    int c = idx & (C - 1);                 // C is a power of two (32 or 64)
    float inv_n = 1.0f / (float)n;
    float mu  = stats[c] * inv_n;
    float var = stats[C + c] * inv_n - mu * mu;
    float v = (y[idx] - mu) * rsqrtf(var + BN_EPS) * g[c] + b[c];
    if (res) v += res[idx];
    if (relu) v = fmaxf(v, 0.0f);
    out[idx] = v;
}

// ---------------------------------------------------------------------------
extern "C" void kernel_launch(void* const* d_in, const int* in_sizes, int n_in_cnt,
                              void* d_out, int out_size) {
    const float* geo  = (const float*)d_in[0];
    const float* col  = (const float*)d_in[1];
    const float* w0   = (const float*)d_in[2];
    const float* w_e1 = (const float*)d_in[3];
    const float* g_e1 = (const float*)d_in[4];
    const float* b_e1 = (const float*)d_in[5];
    const float* w2   = (const float*)d_in[6];
    const float* w_e2 = (const float*)d_in[7];
    const float* g_e2 = (const float*)d_in[8];
    const float* b_e2 = (const float*)d_in[9];
    const int*   m1   = (const int*)d_in[10];
    const int*   m2   = (const int*)d_in[12];
    const int*   m3   = (const int*)d_in[14];
    const int*   m4   = (const int*)d_in[16];

    int n0 = in_sizes[0];
    int n1 = in_sizes[10] / 125;
    int n2 = in_sizes[14] / 27;

    float *X1, *T1, *U1, *X2, *T2, *U2, *stats;
    cudaGetSymbolAddress((void**)&X1, g_X1);
    cudaGetSymbolAddress((void**)&T1, g_T1);
    cudaGetSymbolAddress((void**)&U1, g_U1);
    cudaGetSymbolAddress((void**)&X2, g_X2);
    cudaGetSymbolAddress((void**)&T2, g_T2);
    cudaGetSymbolAddress((void**)&U2, g_U2);
    cudaGetSymbolAddress((void**)&stats, g_stats);

    zero_stats_kernel<<<1, 1024>>>();

    // --- stem: k=5^3 stride-2 conv, Cin=4 -> 32, ReLU ---
    cudaFuncSetAttribute(conv0_kernel,
                         cudaFuncAttributeMaxDynamicSharedMemorySize, 64000);
    conv0_kernel<<<(n1 + 127) / 128, 128, 64000>>>(geo, col, w0, m1, n1, n0, X1);

    // --- enc1: 2 BasicBlocks @ (n1, 32) ---
    for (int i = 0; i < 2; i++) {
        const float* wA = w_e1 + (size_t)(i * 2 + 0) * 27 * 32 * 32;
        const float* wB = w_e1 + (size_t)(i * 2 + 1) * 27 * 32 * 32;
        float* stA = stats + (i * 2 + 0) * 128;
        float* stB = stats + (i * 2 + 1) * 128;

        conv_kernel<32, 32, 1><<<(n1 + 127) / 128, 128>>>(X1, wA, m2, n1, n1, T1, stA);
        bn_apply_kernel<<<((size_t)n1 * 32 + 255) / 256, 256>>>(
            T1, stA, g_e1 + (i * 2 + 0) * 32, b_e1 + (i * 2 + 0) * 32,
            nullptr, T1, n1, 32, 1);

        conv_kernel<32, 32, 1><<<(n1 + 127) / 128, 128>>>(T1, wB, m2, n1, n1, U1, stB);
        bn_apply_kernel<<<((size_t)n1 * 32 + 255) / 256, 256>>>(
            U1, stB, g_e1 + (i * 2 + 1) * 32, b_e1 + (i * 2 + 1) * 32,
            X1, X1, n1, 32, 1);
    }

    // --- conv2: k=3^3 dil=2, 32 -> 64, onto c4 coords (no BN/ReLU) ---
    conv_kernel<32, 64, 2><<<(n2 + 63) / 64, 128>>>(X1, w2, m3, n2, n1, X2, nullptr);

    // --- enc2: 2 BasicBlocks @ (n2, 64) ---
    for (int i = 0; i < 2; i++) {
        const float* wA = w_e2 + (size_t)(i * 2 + 0) * 27 * 64 * 64;
        const float* wB = w_e2 + (size_t)(i * 2 + 1) * 27 * 64 * 64;
        float* stA = stats + (4 + i * 2 + 0) * 128;
        float* stB = stats + (4 + i * 2 + 1) * 128;

        conv_kernel<64, 64, 2><<<(n2 + 63) / 64, 128>>>(X2, wA, m4, n2, n2, T2, stA);
        bn_apply_kernel<<<((size_t)n2 * 64 + 255) / 256, 256>>>(
            T2, stA, g_e2 + (i * 2 + 0) * 64, b_e2 + (i * 2 + 0) * 64,
            nullptr, T2, n2, 64, 1);

        conv_kernel<64, 64, 2><<<(n2 + 63) / 64, 128>>>(T2, wB, m4, n2, n2, U2, stB);
        float* outp = (i == 1) ? (float*)d_out : X2;
        bn_apply_kernel<<<((size_t)n2 * 64 + 255) / 256, 256>>>(
            U2, stB, g_e2 + (i * 2 + 1) * 64, b_e2 + (i * 2 + 1) * 64,
            X2, outp, n2, 64, 1);
    }
}